// round 10
// baseline (speedup 1.0000x reference)
#include <cuda_runtime.h>
#include <cuda_bf16.h>
#include <cstdint>

// Problem constants: B=16, N1=1024, N2=4096, DIM=512
// GEMM1: M=16384, K=1024, N=512.  GEMM2: M=65536, K=512, N=512.

// ---------------- scratch (no allocations allowed) -------------------------
__device__ float g_h1[16384 * 512];
__device__ float g_h2[65536 * 512];
__device__ float g_part[2 * 512 * 512];    // sums | sumsq (rows 0-255 g2, 256-319 g1)
__device__ float g_ss[4 * 512];            // scale1, shift1, scale2, shift2
__device__ __nv_bfloat16 g_w1h[512 * 1024];
__device__ __nv_bfloat16 g_w1l[512 * 1024];
__device__ __nv_bfloat16 g_w2h[512 * 512];
__device__ __nv_bfloat16 g_w2l[512 * 512];

// ---------------- low-level helpers ----------------------------------------
__device__ __forceinline__ uint32_t smem_to_u32(const void* p) {
  uint32_t a;
  asm("{ .reg .u64 t; cvta.to.shared.u64 t, %1; cvt.u32.u64 %0, t; }"
      : "=r"(a) : "l"(p));
  return a;
}
__device__ __forceinline__ void cp_async16(uint32_t dst, const void* src) {
  asm volatile("cp.async.cg.shared.global [%0], [%1], 16;" ::"r"(dst),
               "l"(src));
}
#define CP_COMMIT() asm volatile("cp.async.commit_group;" ::: "memory")
#define CP_WAIT(N) asm volatile("cp.async.wait_group %0;" ::"n"(N) : "memory")

__device__ __forceinline__ void ldsm_x4(uint32_t (&r)[4], uint32_t addr) {
  asm volatile(
      "ldmatrix.sync.aligned.m8n8.x4.shared.b16 {%0,%1,%2,%3}, [%4];"
      : "=r"(r[0]), "=r"(r[1]), "=r"(r[2]), "=r"(r[3])
      : "r"(addr));
}
__device__ __forceinline__ void lds64(float& f0, float& f1, uint32_t addr) {
  asm volatile("ld.shared.v2.f32 {%0,%1}, [%2];"
               : "=f"(f0), "=f"(f1) : "r"(addr));
}
// fp32 pair -> hi bf16x2 (truncation) + lo bf16x2 (residual, RN)
__device__ __forceinline__ void split_pair(float f0, float f1, uint32_t& h,
                                           uint32_t& l) {
  uint32_t u0 = __float_as_uint(f0), u1 = __float_as_uint(f1);
  h = __byte_perm(u0, u1, 0x7632);  // [u1.hi16 | u0.hi16]
  float r0 = f0 - __uint_as_float(u0 & 0xffff0000u);
  float r1 = f1 - __uint_as_float(u1 & 0xffff0000u);
  asm("cvt.rn.bf16x2.f32 %0, %1, %2;" : "=r"(l) : "f"(r1), "f"(r0));
}
__device__ __forceinline__ void mma_bf16(float (&c)[4], const uint32_t (&a)[4],
                                         uint32_t b0, uint32_t b1) {
  asm("mma.sync.aligned.m16n8k16.row.col.f32.bf16.bf16.f32 "
      "{%0,%1,%2,%3}, {%4,%5,%6,%7}, {%8,%9}, {%0,%1,%2,%3};"
      : "+f"(c[0]), "+f"(c[1]), "+f"(c[2]), "+f"(c[3])
      : "r"(a[0]), "r"(a[1]), "r"(a[2]), "r"(a[3]), "r"(b0), "r"(b1));
}

// ---------------------------------------------------------------------------
// Both weights in one launch: W [K,512] -> Wt hi/lo [512,K] transpose + split.
// ---------------------------------------------------------------------------
__global__ void __launch_bounds__(256) wsplit_all(
    const float* __restrict__ W1, __nv_bfloat16* __restrict__ T1h,
    __nv_bfloat16* __restrict__ T1l, const float* __restrict__ W2,
    __nv_bfloat16* __restrict__ T2h, __nv_bfloat16* __restrict__ T2l) {
  __shared__ float tl[32][33];
  const bool first = blockIdx.x < 32;
  const int K = first ? 1024 : 512;
  const float* W = first ? W1 : W2;
  __nv_bfloat16* Th = first ? T1h : T2h;
  __nv_bfloat16* Tl = first ? T1l : T2l;
  int k0 = (first ? blockIdx.x : (blockIdx.x - 32)) * 32;
  int n0 = blockIdx.y * 32;
  int x = threadIdx.x & 31, y = threadIdx.x >> 5;  // 32x8
  for (int i = y; i < 32; i += 8)
    tl[i][x] = W[(size_t)(k0 + i) * 512 + n0 + x];
  __syncthreads();
  for (int i = y; i < 32; i += 8) {
    float v = tl[x][i];  // = W[k0+x][n0+i]
    __nv_bfloat16 h = __float2bfloat16(v);
    __nv_bfloat16 l = __float2bfloat16(v - __bfloat162float(h));
    Th[(size_t)(n0 + i) * K + k0 + x] = h;
    Tl[(size_t)(n0 + i) * K + k0 + x] = l;
  }
}

// ---------------------------------------------------------------------------
// bf16x3 GEMM via mma.sync, BOTH GEMMs in ONE launch (runtime K dispatch on
// blockIdx.x: 0..1023 -> fc2, 1024..1279 -> fc1). A stays fp32 in SMEM; hi/lo
// fragments synthesized at LDS time. CTA tile 256x128, Kc=64, double buffer,
// 512 thr, warp grid 4m x 4n. Epilogue emits per-CTA BN partials.
// ---------------------------------------------------------------------------
static constexpr int A_RS = 288;                  // 64 fp32 + 32B pad
static constexpr int A_BYTES = 256 * A_RS;        // 73728 B
static constexpr int G_RS = 144;                  // B smem row stride bytes
static constexpr int B_TILE = 128 * G_RS;         // 18432 B
static constexpr int G_STAGE = A_BYTES + 2 * B_TILE;  // 110592 B
static constexpr int GEMM_SMEM = 2 * G_STAGE;     // 221184 B

__device__ __forceinline__ void stage_load(
    const float* __restrict__ A, const __nv_bfloat16* __restrict__ Bh,
    const __nv_bfloat16* __restrict__ Bl, int K, int bm, int bn, int k0,
    uint32_t base, int tid) {
  {
    const float* sa = A + (size_t)bm * K;
#pragma unroll
    for (int i = 0; i < 8; i++) {
      int q = tid + i * 512;  // 0..4095
      int row = q >> 4, c4 = q & 15;
      cp_async16(base + row * A_RS + c4 * 16,
                 sa + (size_t)row * K + k0 + c4 * 4);
    }
  }
  {
    const __nv_bfloat16* sbh = Bh + (size_t)bn * K;
    const __nv_bfloat16* sbl = Bl + (size_t)bn * K;
#pragma unroll
    for (int i = 0; i < 2; i++) {
      int q = tid + i * 512;  // 0..1023
      int row = q >> 3, seg = q & 7;
      size_t go = (size_t)row * K + k0 + seg * 8;
      uint32_t so = row * G_RS + seg * 16;
      cp_async16(base + A_BYTES + so, sbh + go);
      cp_async16(base + A_BYTES + B_TILE + so, sbl + go);
    }
  }
}

__device__ __forceinline__ void stage_compute(uint32_t base, int warp_m,
                                              int warp_n, int lid,
                                              float acc[4][4][4]) {
  const uint32_t aF = base + (warp_m * 64 + (lid >> 2)) * A_RS + (lid & 3) * 8;
  const int nrow = warp_n * 32 + (lid & 7) + ((lid >> 4) & 1) * 8;
  const uint32_t b_base =
      base + A_BYTES + nrow * G_RS + ((lid >> 3) & 1) * 16;
#pragma unroll
  for (int kk = 0; kk < 4; kk++) {
    uint32_t ah[4][4], al[4][4], bh[2][4], bl[2][4];
    const uint32_t akk = aF + kk * 64;
#pragma unroll
    for (int i = 0; i < 4; i++) {
      const uint32_t ai = akk + i * (16 * A_RS);
#pragma unroll
      for (int r = 0; r < 4; r++) {
        float f0, f1;
        lds64(f0, f1, ai + (r & 1) * (8 * A_RS) + (r >> 1) * 32);
        split_pair(f0, f1, ah[i][r], al[i][r]);
      }
    }
    const int kb = kk * 32;
#pragma unroll
    for (int jj = 0; jj < 2; jj++) {
      ldsm_x4(bh[jj], b_base + jj * (16 * G_RS) + kb);
      ldsm_x4(bl[jj], b_base + B_TILE + jj * (16 * G_RS) + kb);
    }
#pragma unroll
    for (int i = 0; i < 4; i++)
#pragma unroll
      for (int j = 0; j < 4; j++) {
        const int jj = j >> 1, o = (j & 1) * 2;
        mma_bf16(acc[i][j], ah[i], bh[jj][o], bh[jj][o + 1]);
      }
#pragma unroll
    for (int i = 0; i < 4; i++)
#pragma unroll
      for (int j = 0; j < 4; j++) {
        const int jj = j >> 1, o = (j & 1) * 2;
        mma_bf16(acc[i][j], ah[i], bl[jj][o], bl[jj][o + 1]);
      }
#pragma unroll
    for (int i = 0; i < 4; i++)
#pragma unroll
      for (int j = 0; j < 4; j++) {
        const int jj = j >> 1, o = (j & 1) * 2;
        mma_bf16(acc[i][j], al[i], bh[jj][o], bh[jj][o + 1]);
      }
  }
}

__global__ void __launch_bounds__(512, 1) gemm_all(
    const float* __restrict__ A1, const __nv_bfloat16* __restrict__ B1h,
    const __nv_bfloat16* __restrict__ B1l, const float* __restrict__ bias1,
    float* __restrict__ C1, const float* __restrict__ A2,
    const __nv_bfloat16* __restrict__ B2h,
    const __nv_bfloat16* __restrict__ B2l, const float* __restrict__ bias2,
    float* __restrict__ C2, float* __restrict__ part) {
  extern __shared__ char smem[];
  const uint32_t sb = smem_to_u32(smem);
  const int tid = threadIdx.x;
  const int wid = tid >> 5, lid = tid & 31;
  const int warp_m = wid & 3, warp_n = wid >> 2;

  // dispatch: blocks 0..1023 -> fc2 (K=512); 1024..1279 -> fc1 (K=1024)
  const float* A;
  const __nv_bfloat16 *Bh, *Bl;
  const float* bias;
  float* C;
  int K, bm, bn, prow;
  if (blockIdx.x < 1024) {
    int t = blockIdx.x;
    A = A2; Bh = B2h; Bl = B2l; bias = bias2; C = C2;
    K = 512; bn = (t & 3) * 128; bm = (t >> 2) * 256; prow = t >> 2;
  } else {
    int t = blockIdx.x - 1024;
    A = A1; Bh = B1h; Bl = B1l; bias = bias1; C = C1;
    K = 1024; bn = (t & 3) * 128; bm = (t >> 2) * 256; prow = 256 + (t >> 2);
  }
  const int NS = K / 64;

  float acc[4][4][4];
#pragma unroll
  for (int i = 0; i < 4; i++)
#pragma unroll
    for (int j = 0; j < 4; j++)
#pragma unroll
      for (int r = 0; r < 4; r++) acc[i][j][r] = 0.0f;

  stage_load(A, Bh, Bl, K, bm, bn, 0, sb, tid);
  CP_COMMIT();
  stage_load(A, Bh, Bl, K, bm, bn, 64, sb + G_STAGE, tid);
  CP_COMMIT();

  for (int s = 0; s < NS; s++) {
    CP_WAIT(1);
    __syncthreads();
    stage_compute(sb + (s & 1) * G_STAGE, warp_m, warp_n, lid, acc);
    __syncthreads();
    if (s + 2 < NS) {
      stage_load(A, Bh, Bl, K, bm, bn, (s + 2) * 64,
                 sb + ((s + 2) & 1) * G_STAGE, tid);
      CP_COMMIT();
    }
  }

  // ---- epilogue: +bias, store C, per-CTA column sum/sumsq partials ----
  const int g = lid >> 2, tq = lid & 3;
  float s8[4][2], q8[4][2];
#pragma unroll
  for (int j = 0; j < 4; j++) {
    const int n = bn + warp_n * 32 + j * 8 + tq * 2;
    const float2 bv = *reinterpret_cast<const float2*>(bias + n);
    float sv[2] = {0.0f, 0.0f}, qv[2] = {0.0f, 0.0f};
#pragma unroll
    for (int i = 0; i < 4; i++) {
      const int m = bm + warp_m * 64 + i * 16 + g;
      acc[i][j][0] += bv.x;
      acc[i][j][1] += bv.y;
      acc[i][j][2] += bv.x;
      acc[i][j][3] += bv.y;
      float2 r0 = {acc[i][j][0], acc[i][j][1]};
      float2 r1 = {acc[i][j][2], acc[i][j][3]};
      *reinterpret_cast<float2*>(C + (size_t)m * 512 + n) = r0;
      *reinterpret_cast<float2*>(C + (size_t)(m + 8) * 512 + n) = r1;
#pragma unroll
      for (int p = 0; p < 2; p++) {
        sv[p] += acc[i][j][p] + acc[i][j][p + 2];
        qv[p] += acc[i][j][p] * acc[i][j][p] +
                 acc[i][j][p + 2] * acc[i][j][p + 2];
      }
    }
#pragma unroll
    for (int p = 0; p < 2; p++) {
      float svv = sv[p], qvv = qv[p];
      svv += __shfl_down_sync(0xffffffffu, svv, 16);
      qvv += __shfl_down_sync(0xffffffffu, qvv, 16);
      svv += __shfl_down_sync(0xffffffffu, svv, 8);
      qvv += __shfl_down_sync(0xffffffffu, qvv, 8);
      svv += __shfl_down_sync(0xffffffffu, svv, 4);
      qvv += __shfl_down_sync(0xffffffffu, qvv, 4);
      s8[j][p] = svv;
      q8[j][p] = qvv;
    }
  }
  __syncthreads();  // done with mainloop smem; reuse for reduction
  float* red = reinterpret_cast<float*>(smem);
  if (lid < 4) {
#pragma unroll
    for (int j = 0; j < 4; j++)
#pragma unroll
      for (int p = 0; p < 2; p++) {
        int c = warp_n * 32 + j * 8 + lid * 2 + p;  // lid == tq here
        red[warp_m * 128 + c] = s8[j][p];
        red[512 + warp_m * 128 + c] = q8[j][p];
      }
  }
  __syncthreads();
  if (tid < 128) {
    float s = red[tid] + red[128 + tid] + red[256 + tid] + red[384 + tid];
    float q = red[512 + tid] + red[640 + tid] + red[768 + tid] + red[896 + tid];
    part[(size_t)prow * 512 + bn + tid] = s;
    part[262144 + (size_t)prow * 512 + bn + tid] = q;
  }
}

// ---------------------------------------------------------------------------
// BN stats finalize: ONE launch, one block per (path, channel). grid=1024:
// blocks 0..511 -> path2 (rows 0..255), 512..1023 -> path1 (rows 256..319).
// Parallel load of all partials + deterministic smem tree reduction.
// ---------------------------------------------------------------------------
__global__ void __launch_bounds__(256) stats_finalize_all(
    const float* __restrict__ part, const float* __restrict__ bn1_g,
    const float* __restrict__ bn1_b, const float* __restrict__ bn2_g,
    const float* __restrict__ bn2_b, float* __restrict__ ss) {
  __shared__ float rs[256], rq[256];
  const int t = threadIdx.x;
  const bool path1 = blockIdx.x >= 512;
  const int c = blockIdx.x & 511;
  const int row0 = path1 ? 256 : 0;
  const int NBLK = path1 ? 64 : 256;
  const float invM = path1 ? (1.0f / 16384.0f) : (1.0f / 65536.0f);

  float s = 0.0f, q = 0.0f;
  if (t < NBLK) {
    s = part[(size_t)(row0 + t) * 512 + c];
    q = part[262144 + (size_t)(row0 + t) * 512 + c];
  }
  rs[t] = s;
  rq[t] = q;
  __syncthreads();
#pragma unroll
  for (int off = 128; off > 0; off >>= 1) {
    if (t < off) {
      rs[t] += rs[t + off];
      rq[t] += rq[t + off];
    }
    __syncthreads();
  }
  if (t == 0) {
    float mu = rs[0] * invM;
    float var = rq[0] * invM - mu * mu;
    const float* gamma = path1 ? bn1_g : bn2_g;
    const float* beta = path1 ? bn1_b : bn2_b;
    float* dst = path1 ? ss : (ss + 1024);
    float sc = gamma[c] * rsqrtf(var + 1e-5f);
    dst[c] = sc;
    dst[512 + c] = beta[c] - mu * sc;
  }
}

// ---------------------------------------------------------------------------
// 3-NN inverse-distance interpolation, warp-synchronous: 8 dst points/block,
// one warp per point, xyz1 staged once per block, argmin via shfl (no block
// barriers in the search). Fused BN+ReLU on both feature inputs.
// ---------------------------------------------------------------------------
__global__ void __launch_bounds__(256) interp_add(
    const float* __restrict__ xyz2, const float* __restrict__ xyz1,
    const float* __restrict__ feats1, const float* __restrict__ feats2,
    const float* __restrict__ ss1, const float* __restrict__ ss2,
    float* __restrict__ outF) {
  __shared__ float sx[1024], sy[1024], sz[1024];  // xyz1 SoA (12 KB)
  __shared__ float sd[8][1024];                   // per-warp distances (32 KB)

  const int tid = threadIdx.x;
  const int w = tid >> 5, lane = tid & 31;
  const int b = blockIdx.x >> 9;          // 512 blocks per batch
  const int nb = (blockIdx.x & 511) * 8;  // first dst point of this block

  const float* src = xyz1 + (size_t)b * 3072;
  for (int i = tid; i < 1024; i += 256) {
    sx[i] = src[3 * i + 0];
    sy[i] = src[3 * i + 1];
    sz[i] = src[3 * i + 2];
  }
  __syncthreads();

  const int n = nb + w;
  const float* pd = xyz2 + ((size_t)(b * 4096 + n)) * 3;
  const float px = pd[0], py = pd[1], pz = pd[2];
  const float pp = px * px + py * py + pz * pz;

  float* md = sd[w];
  for (int s = lane; s < 1024; s += 32) {
    float xx = sx[s], yy = sy[s], zz = sz[s];
    md[s] = pp + (xx * xx + yy * yy + zz * zz) -
            2.0f * (px * xx + py * yy + pz * zz);
  }
  __syncwarp();

  // 3 rounds of warp argmin (tie-break: lowest index, matching top_k)
  float bv[3];
  int bi3[3];
#pragma unroll
  for (int round = 0; round < 3; round++) {
    float lv = 1e30f;
    int li = 0x7fffffff;
#pragma unroll
    for (int j = 0; j < 32; j++) {
      int s = lane + j * 32;  // bank-pure: lane -> its own bank
      float v = md[s];
      if (v < lv || (v == lv && s < li)) {
        lv = v;
        li = s;
      }
    }
#pragma unroll
    for (int off = 16; off; off >>= 1) {
      float v2 = __shfl_down_sync(0xffffffffu, lv, off);
      int i2 = __shfl_down_sync(0xffffffffu, li, off);
      if (v2 < lv || (v2 == lv && i2 < li)) {
        lv = v2;
        li = i2;
      }
    }
    lv = __shfl_sync(0xffffffffu, lv, 0);
    li = __shfl_sync(0xffffffffu, li, 0);
    bv[round] = lv;
    bi3[round] = li;
    if (lane == 0) md[li] = 1e30f;
    __syncwarp();
  }

  float w0 = 1.0f / (bv[0] + 1e-8f);
  float w1 = 1.0f / (bv[1] + 1e-8f);
  float w2 = 1.0f / (bv[2] + 1e-8f);
  float inv = 1.0f / (w0 + w1 + w2);
  w0 *= inv;
  w1 *= inv;
  w2 *= inv;

  const float4* f0 =
      reinterpret_cast<const float4*>(feats1 + ((size_t)b * 1024 + bi3[0]) * 512);
  const float4* f1 =
      reinterpret_cast<const float4*>(feats1 + ((size_t)b * 1024 + bi3[1]) * 512);
  const float4* f2 =
      reinterpret_cast<const float4*>(feats1 + ((size_t)b * 1024 + bi3[2]) * 512);
  const float4* g =
      reinterpret_cast<const float4*>(feats2 + ((size_t)(b * 4096 + n)) * 512);
  float4* o = reinterpret_cast<float4*>(outF + ((size_t)(b * 4096 + n)) * 512);
  const float4* SC1 = reinterpret_cast<const float4*>(ss1);
  const float4* SH1 = reinterpret_cast<const float4*>(ss1 + 512);
  const float4* SC2 = reinterpret_cast<const float4*>(ss2);
  const float4* SH2 = reinterpret_cast<const float4*>(ss2 + 512);

#pragma unroll
  for (int c4 = lane; c4 < 128; c4 += 32) {
    float4 a0 = f0[c4], a1 = f1[c4], a2 = f2[c4], gg = g[c4];
    float4 sc1 = SC1[c4], sh1 = SH1[c4], sc2 = SC2[c4], sh2 = SH2[c4];
    a0.x = fmaxf(fmaf(a0.x, sc1.x, sh1.x), 0.0f);
    a0.y = fmaxf(fmaf(a0.y, sc1.y, sh1.y), 0.0f);
    a0.z = fmaxf(fmaf(a0.z, sc1.z, sh1.z), 0.0f);
    a0.w = fmaxf(fmaf(a0.w, sc1.w, sh1.w), 0.0f);
    a1.x = fmaxf(fmaf(a1.x, sc1.x, sh1.x), 0.0f);
    a1.y = fmaxf(fmaf(a1.y, sc1.y, sh1.y), 0.0f);
    a1.z = fmaxf(fmaf(a1.z, sc1.z, sh1.z), 0.0f);
    a1.w = fmaxf(fmaf(a1.w, sc1.w, sh1.w), 0.0f);
    a2.x = fmaxf(fmaf(a2.x, sc1.x, sh1.x), 0.0f);
    a2.y = fmaxf(fmaf(a2.y, sc1.y, sh1.y), 0.0f);
    a2.z = fmaxf(fmaf(a2.z, sc1.z, sh1.z), 0.0f);
    a2.w = fmaxf(fmaf(a2.w, sc1.w, sh1.w), 0.0f);
    gg.x = fmaxf(fmaf(gg.x, sc2.x, sh2.x), 0.0f);
    gg.y = fmaxf(fmaf(gg.y, sc2.y, sh2.y), 0.0f);
    gg.z = fmaxf(fmaf(gg.z, sc2.z, sh2.z), 0.0f);
    gg.w = fmaxf(fmaf(gg.w, sc2.w, sh2.w), 0.0f);
    float4 r;
    r.x = w0 * a0.x + w1 * a1.x + w2 * a2.x + gg.x;
    r.y = w0 * a0.y + w1 * a1.y + w2 * a2.y + gg.y;
    r.z = w0 * a0.z + w1 * a1.z + w2 * a2.z + gg.z;
    r.w = w0 * a0.w + w1 * a1.w + w2 * a2.w + gg.w;
    o[c4] = r;
  }
}

// ---------------------------------------------------------------------------
extern "C" void kernel_launch(void* const* d_in, const int* in_sizes, int n_in,
                              void* d_out, int out_size) {
  const float* xyz1 = (const float*)d_in[0];
  const float* points1 = (const float*)d_in[1];
  const float* xyz2 = (const float*)d_in[2];
  const float* points2 = (const float*)d_in[3];
  const float* fc1_w = (const float*)d_in[4];
  const float* fc1_b = (const float*)d_in[5];
  const float* bn1_g = (const float*)d_in[6];
  const float* bn1_b = (const float*)d_in[7];
  const float* fc2_w = (const float*)d_in[8];
  const float* fc2_b = (const float*)d_in[9];
  const float* bn2_g = (const float*)d_in[10];
  const float* bn2_b = (const float*)d_in[11];
  float* out = (float*)d_out;

  float *h1, *h2, *part, *ss;
  __nv_bfloat16 *w1h, *w1l, *w2h, *w2l;
  cudaGetSymbolAddress((void**)&h1, g_h1);
  cudaGetSymbolAddress((void**)&h2, g_h2);
  cudaGetSymbolAddress((void**)&part, g_part);
  cudaGetSymbolAddress((void**)&ss, g_ss);
  cudaGetSymbolAddress((void**)&w1h, g_w1h);
  cudaGetSymbolAddress((void**)&w1l, g_w1l);
  cudaGetSymbolAddress((void**)&w2h, g_w2h);
  cudaGetSymbolAddress((void**)&w2l, g_w2l);

  cudaFuncSetAttribute(gemm_all, cudaFuncAttributeMaxDynamicSharedMemorySize,
                       GEMM_SMEM);

  const size_t featElems = (size_t)16 * 4096 * 512;
  const size_t totalOut = (size_t)out_size;
  const size_t xyzElems = totalOut > featElems ? totalOut - featElems : 0;

  // launch 1: weight transpose + split
  wsplit_all<<<dim3(48, 16), 256>>>(fc1_w, w1h, w1l, fc2_w, w2h, w2l);

  // launch 2: BOTH GEMMs (fc2 blocks 0..1023, fc1 blocks 1024..1279)
  gemm_all<<<1280, 512, GEMM_SMEM>>>(points1, w1h, w1l, fc1_b, h1, points2,
                                     w2h, w2l, fc2_b, h2, part);

  // launch 3: BN stats for both paths, one block per (path, channel)
  stats_finalize_all<<<1024, 256>>>(part, bn1_g, bn1_b, bn2_g, bn2_b, ss);

  // Output: [xyz2 passthrough | interp(bnrelu(h1)) + bnrelu(h2)]
  if (xyzElems > 0) {
    cudaMemcpyAsync(out, xyz2, xyzElems * sizeof(float),
                    cudaMemcpyDeviceToDevice);
  }
  // launch 4 (+memcpy): interp (8 points/block, warp-synchronous)
  interp_add<<<8192, 256>>>(xyz2, xyz1, h1, h2, ss, ss + 1024,
                            out + xyzElems);
}

// round 11
// speedup vs baseline: 1.5280x; 1.5280x over previous
#include <cuda_runtime.h>
#include <cuda_bf16.h>
#include <cstdint>

// Problem constants: B=16, N1=1024, N2=4096, DIM=512
// GEMM1: M=16384, K=1024, N=512.  GEMM2: M=65536, K=512, N=512.

// ---------------- scratch (no allocations allowed) -------------------------
__device__ float g_h1[16384 * 512];
__device__ float g_h2[65536 * 512];
__device__ float g_part[2 * 512 * 512];    // sums | sumsq (rows 0-255 g2, 256-319 g1)
__device__ float g_ss[4 * 512];            // scale1, shift1, scale2, shift2
__device__ __nv_bfloat16 g_w1h[512 * 1024];
__device__ __nv_bfloat16 g_w1l[512 * 1024];
__device__ __nv_bfloat16 g_w2h[512 * 512];
__device__ __nv_bfloat16 g_w2l[512 * 512];

// ---------------- low-level helpers ----------------------------------------
__device__ __forceinline__ uint32_t smem_to_u32(const void* p) {
  uint32_t a;
  asm("{ .reg .u64 t; cvta.to.shared.u64 t, %1; cvt.u32.u64 %0, t; }"
      : "=r"(a) : "l"(p));
  return a;
}
__device__ __forceinline__ void cp_async16(uint32_t dst, const void* src) {
  asm volatile("cp.async.cg.shared.global [%0], [%1], 16;" ::"r"(dst),
               "l"(src));
}
#define CP_COMMIT() asm volatile("cp.async.commit_group;" ::: "memory")
#define CP_WAIT(N) asm volatile("cp.async.wait_group %0;" ::"n"(N) : "memory")

__device__ __forceinline__ void ldsm_x4(uint32_t (&r)[4], uint32_t addr) {
  asm volatile(
      "ldmatrix.sync.aligned.m8n8.x4.shared.b16 {%0,%1,%2,%3}, [%4];"
      : "=r"(r[0]), "=r"(r[1]), "=r"(r[2]), "=r"(r[3])
      : "r"(addr));
}
__device__ __forceinline__ void lds64(float& f0, float& f1, uint32_t addr) {
  asm volatile("ld.shared.v2.f32 {%0,%1}, [%2];"
               : "=f"(f0), "=f"(f1) : "r"(addr));
}
// fp32 pair -> hi bf16x2 (truncation) + lo bf16x2 (residual, RN)
__device__ __forceinline__ void split_pair(float f0, float f1, uint32_t& h,
                                           uint32_t& l) {
  uint32_t u0 = __float_as_uint(f0), u1 = __float_as_uint(f1);
  h = __byte_perm(u0, u1, 0x7632);  // [u1.hi16 | u0.hi16]
  float r0 = f0 - __uint_as_float(u0 & 0xffff0000u);
  float r1 = f1 - __uint_as_float(u1 & 0xffff0000u);
  asm("cvt.rn.bf16x2.f32 %0, %1, %2;" : "=r"(l) : "f"(r1), "f"(r0));
}
__device__ __forceinline__ void mma_bf16(float (&c)[4], const uint32_t (&a)[4],
                                         uint32_t b0, uint32_t b1) {
  asm("mma.sync.aligned.m16n8k16.row.col.f32.bf16.bf16.f32 "
      "{%0,%1,%2,%3}, {%4,%5,%6,%7}, {%8,%9}, {%0,%1,%2,%3};"
      : "+f"(c[0]), "+f"(c[1]), "+f"(c[2]), "+f"(c[3])
      : "r"(a[0]), "r"(a[1]), "r"(a[2]), "r"(a[3]), "r"(b0), "r"(b1));
}

// ---------------------------------------------------------------------------
// Both weights in one launch: W [K,512] -> Wt hi/lo [512,K] transpose + split.
// ---------------------------------------------------------------------------
__global__ void __launch_bounds__(256) wsplit_all(
    const float* __restrict__ W1, __nv_bfloat16* __restrict__ T1h,
    __nv_bfloat16* __restrict__ T1l, const float* __restrict__ W2,
    __nv_bfloat16* __restrict__ T2h, __nv_bfloat16* __restrict__ T2l) {
  __shared__ float tl[32][33];
  const bool first = blockIdx.x < 32;
  const int K = first ? 1024 : 512;
  const float* W = first ? W1 : W2;
  __nv_bfloat16* Th = first ? T1h : T2h;
  __nv_bfloat16* Tl = first ? T1l : T2l;
  int k0 = (first ? blockIdx.x : (blockIdx.x - 32)) * 32;
  int n0 = blockIdx.y * 32;
  int x = threadIdx.x & 31, y = threadIdx.x >> 5;  // 32x8
  for (int i = y; i < 32; i += 8)
    tl[i][x] = W[(size_t)(k0 + i) * 512 + n0 + x];
  __syncthreads();
  for (int i = y; i < 32; i += 8) {
    float v = tl[x][i];  // = W[k0+x][n0+i]
    __nv_bfloat16 h = __float2bfloat16(v);
    __nv_bfloat16 l = __float2bfloat16(v - __bfloat162float(h));
    Th[(size_t)(n0 + i) * K + k0 + x] = h;
    Tl[(size_t)(n0 + i) * K + k0 + x] = l;
  }
}

// ---------------------------------------------------------------------------
// bf16x3 GEMM via mma.sync, BOTH GEMMs in ONE launch (runtime K dispatch on
// blockIdx.x: 0..1023 -> fc2, 1024..1279 -> fc1). A stays fp32 in SMEM; hi/lo
// fragments synthesized at LDS time. CTA tile 256x128, Kc=64, double buffer,
// 512 thr, warp grid 4m x 4n. Epilogue emits per-CTA BN partials.
// ---------------------------------------------------------------------------
static constexpr int A_RS = 288;                  // 64 fp32 + 32B pad
static constexpr int A_BYTES = 256 * A_RS;        // 73728 B
static constexpr int G_RS = 144;                  // B smem row stride bytes
static constexpr int B_TILE = 128 * G_RS;         // 18432 B
static constexpr int G_STAGE = A_BYTES + 2 * B_TILE;  // 110592 B
static constexpr int GEMM_SMEM = 2 * G_STAGE;     // 221184 B

__device__ __forceinline__ void stage_load(
    const float* __restrict__ A, const __nv_bfloat16* __restrict__ Bh,
    const __nv_bfloat16* __restrict__ Bl, int K, int bm, int bn, int k0,
    uint32_t base, int tid) {
  {
    const float* sa = A + (size_t)bm * K;
#pragma unroll
    for (int i = 0; i < 8; i++) {
      int q = tid + i * 512;  // 0..4095
      int row = q >> 4, c4 = q & 15;
      cp_async16(base + row * A_RS + c4 * 16,
                 sa + (size_t)row * K + k0 + c4 * 4);
    }
  }
  {
    const __nv_bfloat16* sbh = Bh + (size_t)bn * K;
    const __nv_bfloat16* sbl = Bl + (size_t)bn * K;
#pragma unroll
    for (int i = 0; i < 2; i++) {
      int q = tid + i * 512;  // 0..1023
      int row = q >> 3, seg = q & 7;
      size_t go = (size_t)row * K + k0 + seg * 8;
      uint32_t so = row * G_RS + seg * 16;
      cp_async16(base + A_BYTES + so, sbh + go);
      cp_async16(base + A_BYTES + B_TILE + so, sbl + go);
    }
  }
}

__device__ __forceinline__ void stage_compute(uint32_t base, int warp_m,
                                              int warp_n, int lid,
                                              float acc[4][4][4]) {
  const uint32_t aF = base + (warp_m * 64 + (lid >> 2)) * A_RS + (lid & 3) * 8;
  const int nrow = warp_n * 32 + (lid & 7) + ((lid >> 4) & 1) * 8;
  const uint32_t b_base =
      base + A_BYTES + nrow * G_RS + ((lid >> 3) & 1) * 16;
#pragma unroll
  for (int kk = 0; kk < 4; kk++) {
    uint32_t ah[4][4], al[4][4], bh[2][4], bl[2][4];
    const uint32_t akk = aF + kk * 64;
#pragma unroll
    for (int i = 0; i < 4; i++) {
      const uint32_t ai = akk + i * (16 * A_RS);
#pragma unroll
      for (int r = 0; r < 4; r++) {
        float f0, f1;
        lds64(f0, f1, ai + (r & 1) * (8 * A_RS) + (r >> 1) * 32);
        split_pair(f0, f1, ah[i][r], al[i][r]);
      }
    }
    const int kb = kk * 32;
#pragma unroll
    for (int jj = 0; jj < 2; jj++) {
      ldsm_x4(bh[jj], b_base + jj * (16 * G_RS) + kb);
      ldsm_x4(bl[jj], b_base + B_TILE + jj * (16 * G_RS) + kb);
    }
#pragma unroll
    for (int i = 0; i < 4; i++)
#pragma unroll
      for (int j = 0; j < 4; j++) {
        const int jj = j >> 1, o = (j & 1) * 2;
        mma_bf16(acc[i][j], ah[i], bh[jj][o], bh[jj][o + 1]);
      }
#pragma unroll
    for (int i = 0; i < 4; i++)
#pragma unroll
      for (int j = 0; j < 4; j++) {
        const int jj = j >> 1, o = (j & 1) * 2;
        mma_bf16(acc[i][j], ah[i], bl[jj][o], bl[jj][o + 1]);
      }
#pragma unroll
    for (int i = 0; i < 4; i++)
#pragma unroll
      for (int j = 0; j < 4; j++) {
        const int jj = j >> 1, o = (j & 1) * 2;
        mma_bf16(acc[i][j], al[i], bh[jj][o], bh[jj][o + 1]);
      }
  }
}

__global__ void __launch_bounds__(512, 1) gemm_all(
    const float* __restrict__ A1, const __nv_bfloat16* __restrict__ B1h,
    const __nv_bfloat16* __restrict__ B1l, const float* __restrict__ bias1,
    float* __restrict__ C1, const float* __restrict__ A2,
    const __nv_bfloat16* __restrict__ B2h,
    const __nv_bfloat16* __restrict__ B2l, const float* __restrict__ bias2,
    float* __restrict__ C2, float* __restrict__ part) {
  extern __shared__ char smem[];
  const uint32_t sb = smem_to_u32(smem);
  const int tid = threadIdx.x;
  const int wid = tid >> 5, lid = tid & 31;
  const int warp_m = wid & 3, warp_n = wid >> 2;

  // dispatch: blocks 0..1023 -> fc2 (K=512); 1024..1279 -> fc1 (K=1024)
  const float* A;
  const __nv_bfloat16 *Bh, *Bl;
  const float* bias;
  float* C;
  int K, bm, bn, prow;
  if (blockIdx.x < 1024) {
    int t = blockIdx.x;
    A = A2; Bh = B2h; Bl = B2l; bias = bias2; C = C2;
    K = 512; bn = (t & 3) * 128; bm = (t >> 2) * 256; prow = t >> 2;
  } else {
    int t = blockIdx.x - 1024;
    A = A1; Bh = B1h; Bl = B1l; bias = bias1; C = C1;
    K = 1024; bn = (t & 3) * 128; bm = (t >> 2) * 256; prow = 256 + (t >> 2);
  }
  const int NS = K / 64;

  float acc[4][4][4];
#pragma unroll
  for (int i = 0; i < 4; i++)
#pragma unroll
    for (int j = 0; j < 4; j++)
#pragma unroll
      for (int r = 0; r < 4; r++) acc[i][j][r] = 0.0f;

  stage_load(A, Bh, Bl, K, bm, bn, 0, sb, tid);
  CP_COMMIT();
  stage_load(A, Bh, Bl, K, bm, bn, 64, sb + G_STAGE, tid);
  CP_COMMIT();

  for (int s = 0; s < NS; s++) {
    CP_WAIT(1);
    __syncthreads();
    stage_compute(sb + (s & 1) * G_STAGE, warp_m, warp_n, lid, acc);
    __syncthreads();
    if (s + 2 < NS) {
      stage_load(A, Bh, Bl, K, bm, bn, (s + 2) * 64,
                 sb + ((s + 2) & 1) * G_STAGE, tid);
      CP_COMMIT();
    }
  }

  // ---- epilogue: +bias, store C, per-CTA column sum/sumsq partials ----
  const int g = lid >> 2, tq = lid & 3;
  float s8[4][2], q8[4][2];
#pragma unroll
  for (int j = 0; j < 4; j++) {
    const int n = bn + warp_n * 32 + j * 8 + tq * 2;
    const float2 bv = *reinterpret_cast<const float2*>(bias + n);
    float sv[2] = {0.0f, 0.0f}, qv[2] = {0.0f, 0.0f};
#pragma unroll
    for (int i = 0; i < 4; i++) {
      const int m = bm + warp_m * 64 + i * 16 + g;
      acc[i][j][0] += bv.x;
      acc[i][j][1] += bv.y;
      acc[i][j][2] += bv.x;
      acc[i][j][3] += bv.y;
      float2 r0 = {acc[i][j][0], acc[i][j][1]};
      float2 r1 = {acc[i][j][2], acc[i][j][3]};
      *reinterpret_cast<float2*>(C + (size_t)m * 512 + n) = r0;
      *reinterpret_cast<float2*>(C + (size_t)(m + 8) * 512 + n) = r1;
#pragma unroll
      for (int p = 0; p < 2; p++) {
        sv[p] += acc[i][j][p] + acc[i][j][p + 2];
        qv[p] += acc[i][j][p] * acc[i][j][p] +
                 acc[i][j][p + 2] * acc[i][j][p + 2];
      }
    }
#pragma unroll
    for (int p = 0; p < 2; p++) {
      float svv = sv[p], qvv = qv[p];
      svv += __shfl_down_sync(0xffffffffu, svv, 16);
      qvv += __shfl_down_sync(0xffffffffu, qvv, 16);
      svv += __shfl_down_sync(0xffffffffu, svv, 8);
      qvv += __shfl_down_sync(0xffffffffu, qvv, 8);
      svv += __shfl_down_sync(0xffffffffu, svv, 4);
      qvv += __shfl_down_sync(0xffffffffu, qvv, 4);
      s8[j][p] = svv;
      q8[j][p] = qvv;
    }
  }
  __syncthreads();  // done with mainloop smem; reuse for reduction
  float* red = reinterpret_cast<float*>(smem);
  if (lid < 4) {
#pragma unroll
    for (int j = 0; j < 4; j++)
#pragma unroll
      for (int p = 0; p < 2; p++) {
        int c = warp_n * 32 + j * 8 + lid * 2 + p;  // lid == tq here
        red[warp_m * 128 + c] = s8[j][p];
        red[512 + warp_m * 128 + c] = q8[j][p];
      }
  }
  __syncthreads();
  if (tid < 128) {
    float s = red[tid] + red[128 + tid] + red[256 + tid] + red[384 + tid];
    float q = red[512 + tid] + red[640 + tid] + red[768 + tid] + red[896 + tid];
    part[(size_t)prow * 512 + bn + tid] = s;
    part[262144 + (size_t)prow * 512 + bn + tid] = q;
  }
}

// ---------------------------------------------------------------------------
// BN stats finalize: ONE launch, one block per (path, channel). grid=1024:
// blocks 0..511 -> path2 (rows 0..255), 512..1023 -> path1 (rows 256..319).
// ---------------------------------------------------------------------------
__global__ void __launch_bounds__(256) stats_finalize_all(
    const float* __restrict__ part, const float* __restrict__ bn1_g,
    const float* __restrict__ bn1_b, const float* __restrict__ bn2_g,
    const float* __restrict__ bn2_b, float* __restrict__ ss) {
  __shared__ float rs[256], rq[256];
  const int t = threadIdx.x;
  const bool path1 = blockIdx.x >= 512;
  const int c = blockIdx.x & 511;
  const int row0 = path1 ? 256 : 0;
  const int NBLK = path1 ? 64 : 256;
  const float invM = path1 ? (1.0f / 16384.0f) : (1.0f / 65536.0f);

  float s = 0.0f, q = 0.0f;
  if (t < NBLK) {
    s = part[(size_t)(row0 + t) * 512 + c];
    q = part[262144 + (size_t)(row0 + t) * 512 + c];
  }
  rs[t] = s;
  rq[t] = q;
  __syncthreads();
#pragma unroll
  for (int off = 128; off > 0; off >>= 1) {
    if (t < off) {
      rs[t] += rs[t + off];
      rq[t] += rq[t + off];
    }
    __syncthreads();
  }
  if (t == 0) {
    float mu = rs[0] * invM;
    float var = rq[0] * invM - mu * mu;
    const float* gamma = path1 ? bn1_g : bn2_g;
    const float* beta = path1 ? bn1_b : bn2_b;
    float* dst = path1 ? ss : (ss + 1024);
    float sc = gamma[c] * rsqrtf(var + 1e-5f);
    dst[c] = sc;
    dst[512 + c] = beta[c] - mu * sc;
  }
}

// ---------------------------------------------------------------------------
// 3-NN inverse-distance interpolation, warp-synchronous, REGISTER-RESIDENT
// distances: 8 dst points/block, one warp/point, 32 dists per lane in regs.
// Argmin rounds: fminf chain + shfl-xor reduce + register equality scan
// (min value, then min index — identical tie-break to top_k). No smem
// distance array. Fused BN+ReLU on both feature inputs.
// ---------------------------------------------------------------------------
__global__ void __launch_bounds__(256) interp_add(
    const float* __restrict__ xyz2, const float* __restrict__ xyz1,
    const float* __restrict__ feats1, const float* __restrict__ feats2,
    const float* __restrict__ ss1, const float* __restrict__ ss2,
    float* __restrict__ outF) {
  __shared__ float sx[1024], sy[1024], sz[1024];  // xyz1 SoA (12 KB)

  const int tid = threadIdx.x;
  const int w = tid >> 5, lane = tid & 31;
  const int b = blockIdx.x >> 9;          // 512 blocks per batch
  const int nb = (blockIdx.x & 511) * 8;  // first dst point of this block

  const float* src = xyz1 + (size_t)b * 3072;
  for (int i = tid; i < 1024; i += 256) {
    sx[i] = src[3 * i + 0];
    sy[i] = src[3 * i + 1];
    sz[i] = src[3 * i + 2];
  }
  __syncthreads();

  const int n = nb + w;
  const float* pd = xyz2 + ((size_t)(b * 4096 + n)) * 3;
  const float px = pd[0], py = pd[1], pz = pd[2];
  const float pp = px * px + py * py + pz * pz;

  // distances for srcs lane+32*j, held in registers
  float d[32];
#pragma unroll
  for (int j = 0; j < 32; j++) {
    int s = lane + j * 32;
    float xx = sx[s], yy = sy[s], zz = sz[s];
    d[j] = pp + (xx * xx + yy * yy + zz * zz) -
           2.0f * (px * xx + py * yy + pz * zz);
  }

  float bv[3];
  int bi3[3];
#pragma unroll
  for (int round = 0; round < 3; round++) {
    // per-lane min value
    float m = d[0];
#pragma unroll
    for (int j = 1; j < 32; j++) m = fminf(m, d[j]);
    // warp min (xor butterfly -> all lanes hold global min)
#pragma unroll
    for (int off = 16; off; off >>= 1)
      m = fminf(m, __shfl_xor_sync(0xffffffffu, m, off));
    // min index among equal values
    int li = 0x7fffffff;
#pragma unroll
    for (int j = 0; j < 32; j++)
      if (d[j] == m) li = min(li, lane + j * 32);
#pragma unroll
    for (int off = 16; off; off >>= 1)
      li = min(li, __shfl_xor_sync(0xffffffffu, li, off));
    bv[round] = m;
    bi3[round] = li;
    // exclude found element (owner lane sets its slot to +inf)
    if ((li & 31) == lane) {
      const int slot = li >> 5;
#pragma unroll
      for (int j = 0; j < 32; j++)
        if (j == slot) d[j] = 1e30f;
    }
  }

  float w0 = 1.0f / (bv[0] + 1e-8f);
  float w1 = 1.0f / (bv[1] + 1e-8f);
  float w2 = 1.0f / (bv[2] + 1e-8f);
  float inv = 1.0f / (w0 + w1 + w2);
  w0 *= inv;
  w1 *= inv;
  w2 *= inv;

  const float4* f0 =
      reinterpret_cast<const float4*>(feats1 + ((size_t)b * 1024 + bi3[0]) * 512);
  const float4* f1 =
      reinterpret_cast<const float4*>(feats1 + ((size_t)b * 1024 + bi3[1]) * 512);
  const float4* f2 =
      reinterpret_cast<const float4*>(feats1 + ((size_t)b * 1024 + bi3[2]) * 512);
  const float4* g =
      reinterpret_cast<const float4*>(feats2 + ((size_t)(b * 4096 + n)) * 512);
  float4* o = reinterpret_cast<float4*>(outF + ((size_t)(b * 4096 + n)) * 512);
  const float4* SC1 = reinterpret_cast<const float4*>(ss1);
  const float4* SH1 = reinterpret_cast<const float4*>(ss1 + 512);
  const float4* SC2 = reinterpret_cast<const float4*>(ss2);
  const float4* SH2 = reinterpret_cast<const float4*>(ss2 + 512);

#pragma unroll
  for (int c4 = lane; c4 < 128; c4 += 32) {
    float4 a0 = f0[c4], a1 = f1[c4], a2 = f2[c4], gg = g[c4];
    float4 sc1 = SC1[c4], sh1 = SH1[c4], sc2 = SC2[c4], sh2 = SH2[c4];
    a0.x = fmaxf(fmaf(a0.x, sc1.x, sh1.x), 0.0f);
    a0.y = fmaxf(fmaf(a0.y, sc1.y, sh1.y), 0.0f);
    a0.z = fmaxf(fmaf(a0.z, sc1.z, sh1.z), 0.0f);
    a0.w = fmaxf(fmaf(a0.w, sc1.w, sh1.w), 0.0f);
    a1.x = fmaxf(fmaf(a1.x, sc1.x, sh1.x), 0.0f);
    a1.y = fmaxf(fmaf(a1.y, sc1.y, sh1.y), 0.0f);
    a1.z = fmaxf(fmaf(a1.z, sc1.z, sh1.z), 0.0f);
    a1.w = fmaxf(fmaf(a1.w, sc1.w, sh1.w), 0.0f);
    a2.x = fmaxf(fmaf(a2.x, sc1.x, sh1.x), 0.0f);
    a2.y = fmaxf(fmaf(a2.y, sc1.y, sh1.y), 0.0f);
    a2.z = fmaxf(fmaf(a2.z, sc1.z, sh1.z), 0.0f);
    a2.w = fmaxf(fmaf(a2.w, sc1.w, sh1.w), 0.0f);
    gg.x = fmaxf(fmaf(gg.x, sc2.x, sh2.x), 0.0f);
    gg.y = fmaxf(fmaf(gg.y, sc2.y, sh2.y), 0.0f);
    gg.z = fmaxf(fmaf(gg.z, sc2.z, sh2.z), 0.0f);
    gg.w = fmaxf(fmaf(gg.w, sc2.w, sh2.w), 0.0f);
    float4 r;
    r.x = w0 * a0.x + w1 * a1.x + w2 * a2.x + gg.x;
    r.y = w0 * a0.y + w1 * a1.y + w2 * a2.y + gg.y;
    r.z = w0 * a0.z + w1 * a1.z + w2 * a2.z + gg.z;
    r.w = w0 * a0.w + w1 * a1.w + w2 * a2.w + gg.w;
    o[c4] = r;
  }
}

// ---------------------------------------------------------------------------
extern "C" void kernel_launch(void* const* d_in, const int* in_sizes, int n_in,
                              void* d_out, int out_size) {
  const float* xyz1 = (const float*)d_in[0];
  const float* points1 = (const float*)d_in[1];
  const float* xyz2 = (const float*)d_in[2];
  const float* points2 = (const float*)d_in[3];
  const float* fc1_w = (const float*)d_in[4];
  const float* fc1_b = (const float*)d_in[5];
  const float* bn1_g = (const float*)d_in[6];
  const float* bn1_b = (const float*)d_in[7];
  const float* fc2_w = (const float*)d_in[8];
  const float* fc2_b = (const float*)d_in[9];
  const float* bn2_g = (const float*)d_in[10];
  const float* bn2_b = (const float*)d_in[11];
  float* out = (float*)d_out;

  float *h1, *h2, *part, *ss;
  __nv_bfloat16 *w1h, *w1l, *w2h, *w2l;
  cudaGetSymbolAddress((void**)&h1, g_h1);
  cudaGetSymbolAddress((void**)&h2, g_h2);
  cudaGetSymbolAddress((void**)&part, g_part);
  cudaGetSymbolAddress((void**)&ss, g_ss);
  cudaGetSymbolAddress((void**)&w1h, g_w1h);
  cudaGetSymbolAddress((void**)&w1l, g_w1l);
  cudaGetSymbolAddress((void**)&w2h, g_w2h);
  cudaGetSymbolAddress((void**)&w2l, g_w2l);

  cudaFuncSetAttribute(gemm_all, cudaFuncAttributeMaxDynamicSharedMemorySize,
                       GEMM_SMEM);

  const size_t featElems = (size_t)16 * 4096 * 512;
  const size_t totalOut = (size_t)out_size;
  const size_t xyzElems = totalOut > featElems ? totalOut - featElems : 0;

  // launch 1: weight transpose + split
  wsplit_all<<<dim3(48, 16), 256>>>(fc1_w, w1h, w1l, fc2_w, w2h, w2l);

  // launch 2: BOTH GEMMs (fc2 blocks 0..1023, fc1 blocks 1024..1279)
  gemm_all<<<1280, 512, GEMM_SMEM>>>(points1, w1h, w1l, fc1_b, h1, points2,
                                     w2h, w2l, fc2_b, h2, part);

  // launch 3: BN stats for both paths, one block per (path, channel)
  stats_finalize_all<<<1024, 256>>>(part, bn1_g, bn1_b, bn2_g, bn2_b, ss);

  // Output: [xyz2 passthrough | interp(bnrelu(h1)) + bnrelu(h2)]
  if (xyzElems > 0) {
    cudaMemcpyAsync(out, xyz2, xyzElems * sizeof(float),
                    cudaMemcpyDeviceToDevice);
  }
  // launch 4 (+memcpy): interp (register-resident argmin)
  interp_add<<<8192, 256>>>(xyz2, xyz1, h1, h2, ss, ss + 1024,
                            out + xyzElems);
}

// round 13
// speedup vs baseline: 1.5622x; 1.0224x over previous
#include <cuda_runtime.h>
#include <cuda_bf16.h>
#include <cstdint>

// Problem constants: B=16, N1=1024, N2=4096, DIM=512
// GEMM1: M=16384, K=1024, N=512.  GEMM2: M=65536, K=512, N=512.

// ---------------- scratch (no allocations allowed) -------------------------
__device__ float g_h1[16384 * 512];
__device__ float g_h2[65536 * 512];
__device__ float g_part[2 * 512 * 512];    // sums | sumsq (rows 0-255 g2, 256-319 g1)
__device__ float g_ss[4 * 512];            // scale1, shift1, scale2, shift2
__device__ float4 g_kw[65536];             // 3-NN weights per dst point
__device__ int4 g_ki[65536];               // 3-NN global feats1 row ids
__device__ __nv_bfloat16 g_w1h[512 * 1024];
__device__ __nv_bfloat16 g_w1l[512 * 1024];
__device__ __nv_bfloat16 g_w2h[512 * 512];
__device__ __nv_bfloat16 g_w2l[512 * 512];

// ---------------- low-level helpers ----------------------------------------
__device__ __forceinline__ uint32_t smem_to_u32(const void* p) {
  uint32_t a;
  asm("{ .reg .u64 t; cvta.to.shared.u64 t, %1; cvt.u32.u64 %0, t; }"
      : "=r"(a) : "l"(p));
  return a;
}
__device__ __forceinline__ void cp_async16(uint32_t dst, const void* src) {
  asm volatile("cp.async.cg.shared.global [%0], [%1], 16;" ::"r"(dst),
               "l"(src));
}
#define CP_COMMIT() asm volatile("cp.async.commit_group;" ::: "memory")
#define CP_WAIT(N) asm volatile("cp.async.wait_group %0;" ::"n"(N) : "memory")

__device__ __forceinline__ void ldsm_x4(uint32_t (&r)[4], uint32_t addr) {
  asm volatile(
      "ldmatrix.sync.aligned.m8n8.x4.shared.b16 {%0,%1,%2,%3}, [%4];"
      : "=r"(r[0]), "=r"(r[1]), "=r"(r[2]), "=r"(r[3])
      : "r"(addr));
}
__device__ __forceinline__ void lds64(float& f0, float& f1, uint32_t addr) {
  asm volatile("ld.shared.v2.f32 {%0,%1}, [%2];"
               : "=f"(f0), "=f"(f1) : "r"(addr));
}
// fp32 pair -> hi bf16x2 (truncation) + lo bf16x2 (residual, RN)
__device__ __forceinline__ void split_pair(float f0, float f1, uint32_t& h,
                                           uint32_t& l) {
  uint32_t u0 = __float_as_uint(f0), u1 = __float_as_uint(f1);
  h = __byte_perm(u0, u1, 0x7632);  // [u1.hi16 | u0.hi16]
  float r0 = f0 - __uint_as_float(u0 & 0xffff0000u);
  float r1 = f1 - __uint_as_float(u1 & 0xffff0000u);
  asm("cvt.rn.bf16x2.f32 %0, %1, %2;" : "=r"(l) : "f"(r1), "f"(r0));
}
__device__ __forceinline__ void mma_bf16(float (&c)[4], const uint32_t (&a)[4],
                                         uint32_t b0, uint32_t b1) {
  asm("mma.sync.aligned.m16n8k16.row.col.f32.bf16.bf16.f32 "
      "{%0,%1,%2,%3}, {%4,%5,%6,%7}, {%8,%9}, {%0,%1,%2,%3};"
      : "+f"(c[0]), "+f"(c[1]), "+f"(c[2]), "+f"(c[3])
      : "r"(a[0]), "r"(a[1]), "r"(a[2]), "r"(a[3]), "r"(b0), "r"(b1));
}

// ---------------------------------------------------------------------------
// Both weights in one launch: W [K,512] -> Wt hi/lo [512,K] transpose + split.
// ---------------------------------------------------------------------------
__global__ void __launch_bounds__(256) wsplit_all(
    const float* __restrict__ W1, __nv_bfloat16* __restrict__ T1h,
    __nv_bfloat16* __restrict__ T1l, const float* __restrict__ W2,
    __nv_bfloat16* __restrict__ T2h, __nv_bfloat16* __restrict__ T2l) {
  __shared__ float tl[32][33];
  const bool first = blockIdx.x < 32;
  const int K = first ? 1024 : 512;
  const float* W = first ? W1 : W2;
  __nv_bfloat16* Th = first ? T1h : T2h;
  __nv_bfloat16* Tl = first ? T1l : T2l;
  int k0 = (first ? blockIdx.x : (blockIdx.x - 32)) * 32;
  int n0 = blockIdx.y * 32;
  int x = threadIdx.x & 31, y = threadIdx.x >> 5;  // 32x8
  for (int i = y; i < 32; i += 8)
    tl[i][x] = W[(size_t)(k0 + i) * 512 + n0 + x];
  __syncthreads();
  for (int i = y; i < 32; i += 8) {
    float v = tl[x][i];  // = W[k0+x][n0+i]
    __nv_bfloat16 h = __float2bfloat16(v);
    __nv_bfloat16 l = __float2bfloat16(v - __bfloat162float(h));
    Th[(size_t)(n0 + i) * K + k0 + x] = h;
    Tl[(size_t)(n0 + i) * K + k0 + x] = l;
  }
}

// ---------------------------------------------------------------------------
// bf16x3 GEMM via mma.sync, BOTH GEMMs in ONE launch (runtime K dispatch on
// blockIdx.x: 0..1023 -> fc2, 1024..1279 -> fc1). A stays fp32 in SMEM; hi/lo
// fragments synthesized at LDS time. CTA tile 256x128, Kc=64, double buffer,
// 512 thr, warp grid 4m x 4n. Epilogue emits per-CTA BN partials.
// ---------------------------------------------------------------------------
static constexpr int A_RS = 288;                  // 64 fp32 + 32B pad
static constexpr int A_BYTES = 256 * A_RS;        // 73728 B
static constexpr int G_RS = 144;                  // B smem row stride bytes
static constexpr int B_TILE = 128 * G_RS;         // 18432 B
static constexpr int G_STAGE = A_BYTES + 2 * B_TILE;  // 110592 B
static constexpr int GEMM_SMEM = 2 * G_STAGE;     // 221184 B

__device__ __forceinline__ void stage_load(
    const float* __restrict__ A, const __nv_bfloat16* __restrict__ Bh,
    const __nv_bfloat16* __restrict__ Bl, int K, int bm, int bn, int k0,
    uint32_t base, int tid) {
  {
    const float* sa = A + (size_t)bm * K;
#pragma unroll
    for (int i = 0; i < 8; i++) {
      int q = tid + i * 512;  // 0..4095
      int row = q >> 4, c4 = q & 15;
      cp_async16(base + row * A_RS + c4 * 16,
                 sa + (size_t)row * K + k0 + c4 * 4);
    }
  }
  {
    const __nv_bfloat16* sbh = Bh + (size_t)bn * K;
    const __nv_bfloat16* sbl = Bl + (size_t)bn * K;
#pragma unroll
    for (int i = 0; i < 2; i++) {
      int q = tid + i * 512;  // 0..1023
      int row = q >> 3, seg = q & 7;
      size_t go = (size_t)row * K + k0 + seg * 8;
      uint32_t so = row * G_RS + seg * 16;
      cp_async16(base + A_BYTES + so, sbh + go);
      cp_async16(base + A_BYTES + B_TILE + so, sbl + go);
    }
  }
}

__device__ __forceinline__ void stage_compute(uint32_t base, int warp_m,
                                              int warp_n, int lid,
                                              float acc[4][4][4]) {
  const uint32_t aF = base + (warp_m * 64 + (lid >> 2)) * A_RS + (lid & 3) * 8;
  const int nrow = warp_n * 32 + (lid & 7) + ((lid >> 4) & 1) * 8;
  const uint32_t b_base =
      base + A_BYTES + nrow * G_RS + ((lid >> 3) & 1) * 16;
#pragma unroll
  for (int kk = 0; kk < 4; kk++) {
    uint32_t ah[4][4], al[4][4], bh[2][4], bl[2][4];
    const uint32_t akk = aF + kk * 64;
#pragma unroll
    for (int i = 0; i < 4; i++) {
      const uint32_t ai = akk + i * (16 * A_RS);
#pragma unroll
      for (int r = 0; r < 4; r++) {
        float f0, f1;
        lds64(f0, f1, ai + (r & 1) * (8 * A_RS) + (r >> 1) * 32);
        split_pair(f0, f1, ah[i][r], al[i][r]);
      }
    }
    const int kb = kk * 32;
#pragma unroll
    for (int jj = 0; jj < 2; jj++) {
      ldsm_x4(bh[jj], b_base + jj * (16 * G_RS) + kb);
      ldsm_x4(bl[jj], b_base + B_TILE + jj * (16 * G_RS) + kb);
    }
#pragma unroll
    for (int i = 0; i < 4; i++)
#pragma unroll
      for (int j = 0; j < 4; j++) {
        const int jj = j >> 1, o = (j & 1) * 2;
        mma_bf16(acc[i][j], ah[i], bh[jj][o], bh[jj][o + 1]);
      }
#pragma unroll
    for (int i = 0; i < 4; i++)
#pragma unroll
      for (int j = 0; j < 4; j++) {
        const int jj = j >> 1, o = (j & 1) * 2;
        mma_bf16(acc[i][j], ah[i], bl[jj][o], bl[jj][o + 1]);
      }
#pragma unroll
    for (int i = 0; i < 4; i++)
#pragma unroll
      for (int j = 0; j < 4; j++) {
        const int jj = j >> 1, o = (j & 1) * 2;
        mma_bf16(acc[i][j], al[i], bh[jj][o], bh[jj][o + 1]);
      }
  }
}

__global__ void __launch_bounds__(512, 1) gemm_all(
    const float* __restrict__ A1, const __nv_bfloat16* __restrict__ B1h,
    const __nv_bfloat16* __restrict__ B1l, const float* __restrict__ bias1,
    float* __restrict__ C1, const float* __restrict__ A2,
    const __nv_bfloat16* __restrict__ B2h,
    const __nv_bfloat16* __restrict__ B2l, const float* __restrict__ bias2,
    float* __restrict__ C2, float* __restrict__ part) {
  extern __shared__ char smem[];
  const uint32_t sb = smem_to_u32(smem);
  const int tid = threadIdx.x;
  const int wid = tid >> 5, lid = tid & 31;
  const int warp_m = wid & 3, warp_n = wid >> 2;

  // dispatch: blocks 0..1023 -> fc2 (K=512); 1024..1279 -> fc1 (K=1024)
  const float* A;
  const __nv_bfloat16 *Bh, *Bl;
  const float* bias;
  float* C;
  int K, bm, bn, prow;
  if (blockIdx.x < 1024) {
    int t = blockIdx.x;
    A = A2; Bh = B2h; Bl = B2l; bias = bias2; C = C2;
    K = 512; bn = (t & 3) * 128; bm = (t >> 2) * 256; prow = t >> 2;
  } else {
    int t = blockIdx.x - 1024;
    A = A1; Bh = B1h; Bl = B1l; bias = bias1; C = C1;
    K = 1024; bn = (t & 3) * 128; bm = (t >> 2) * 256; prow = 256 + (t >> 2);
  }
  const int NS = K / 64;

  float acc[4][4][4];
#pragma unroll
  for (int i = 0; i < 4; i++)
#pragma unroll
    for (int j = 0; j < 4; j++)
#pragma unroll
      for (int r = 0; r < 4; r++) acc[i][j][r] = 0.0f;

  stage_load(A, Bh, Bl, K, bm, bn, 0, sb, tid);
  CP_COMMIT();
  stage_load(A, Bh, Bl, K, bm, bn, 64, sb + G_STAGE, tid);
  CP_COMMIT();

  for (int s = 0; s < NS; s++) {
    CP_WAIT(1);
    __syncthreads();
    stage_compute(sb + (s & 1) * G_STAGE, warp_m, warp_n, lid, acc);
    __syncthreads();
    if (s + 2 < NS) {
      stage_load(A, Bh, Bl, K, bm, bn, (s + 2) * 64,
                 sb + ((s + 2) & 1) * G_STAGE, tid);
      CP_COMMIT();
    }
  }

  // ---- epilogue: +bias, store C, per-CTA column sum/sumsq partials ----
  const int g = lid >> 2, tq = lid & 3;
  float s8[4][2], q8[4][2];
#pragma unroll
  for (int j = 0; j < 4; j++) {
    const int n = bn + warp_n * 32 + j * 8 + tq * 2;
    const float2 bv = *reinterpret_cast<const float2*>(bias + n);
    float sv[2] = {0.0f, 0.0f}, qv[2] = {0.0f, 0.0f};
#pragma unroll
    for (int i = 0; i < 4; i++) {
      const int m = bm + warp_m * 64 + i * 16 + g;
      acc[i][j][0] += bv.x;
      acc[i][j][1] += bv.y;
      acc[i][j][2] += bv.x;
      acc[i][j][3] += bv.y;
      float2 r0 = {acc[i][j][0], acc[i][j][1]};
      float2 r1 = {acc[i][j][2], acc[i][j][3]};
      *reinterpret_cast<float2*>(C + (size_t)m * 512 + n) = r0;
      *reinterpret_cast<float2*>(C + (size_t)(m + 8) * 512 + n) = r1;
#pragma unroll
      for (int p = 0; p < 2; p++) {
        sv[p] += acc[i][j][p] + acc[i][j][p + 2];
        qv[p] += acc[i][j][p] * acc[i][j][p] +
                 acc[i][j][p + 2] * acc[i][j][p + 2];
      }
    }
#pragma unroll
    for (int p = 0; p < 2; p++) {
      float svv = sv[p], qvv = qv[p];
      svv += __shfl_down_sync(0xffffffffu, svv, 16);
      qvv += __shfl_down_sync(0xffffffffu, qvv, 16);
      svv += __shfl_down_sync(0xffffffffu, svv, 8);
      qvv += __shfl_down_sync(0xffffffffu, qvv, 8);
      svv += __shfl_down_sync(0xffffffffu, svv, 4);
      qvv += __shfl_down_sync(0xffffffffu, qvv, 4);
      s8[j][p] = svv;
      q8[j][p] = qvv;
    }
  }
  __syncthreads();  // done with mainloop smem; reuse for reduction
  float* red = reinterpret_cast<float*>(smem);
  if (lid < 4) {
#pragma unroll
    for (int j = 0; j < 4; j++)
#pragma unroll
      for (int p = 0; p < 2; p++) {
        int c = warp_n * 32 + j * 8 + lid * 2 + p;  // lid == tq here
        red[warp_m * 128 + c] = s8[j][p];
        red[512 + warp_m * 128 + c] = q8[j][p];
      }
  }
  __syncthreads();
  if (tid < 128) {
    float s = red[tid] + red[128 + tid] + red[256 + tid] + red[384 + tid];
    float q = red[512 + tid] + red[640 + tid] + red[768 + tid] + red[896 + tid];
    part[(size_t)prow * 512 + bn + tid] = s;
    part[262144 + (size_t)prow * 512 + bn + tid] = q;
  }
}

// ---------------------------------------------------------------------------
// BN stats finalize: ONE launch, one block per (path, channel). grid=1024:
// blocks 0..511 -> path2 (rows 0..255), 512..1023 -> path1 (rows 256..319).
// ---------------------------------------------------------------------------
__global__ void __launch_bounds__(256) stats_finalize_all(
    const float* __restrict__ part, const float* __restrict__ bn1_g,
    const float* __restrict__ bn1_b, const float* __restrict__ bn2_g,
    const float* __restrict__ bn2_b, float* __restrict__ ss) {
  __shared__ float rs[256], rq[256];
  const int t = threadIdx.x;
  const bool path1 = blockIdx.x >= 512;
  const int c = blockIdx.x & 511;
  const int row0 = path1 ? 256 : 0;
  const int NBLK = path1 ? 64 : 256;
  const float invM = path1 ? (1.0f / 16384.0f) : (1.0f / 65536.0f);

  float s = 0.0f, q = 0.0f;
  if (t < NBLK) {
    s = part[(size_t)(row0 + t) * 512 + c];
    q = part[262144 + (size_t)(row0 + t) * 512 + c];
  }
  rs[t] = s;
  rq[t] = q;
  __syncthreads();
#pragma unroll
  for (int off = 128; off > 0; off >>= 1) {
    if (t < off) {
      rs[t] += rs[t + off];
      rq[t] += rq[t + off];
    }
    __syncthreads();
  }
  if (t == 0) {
    float mu = rs[0] * invM;
    float var = rq[0] * invM - mu * mu;
    const float* gamma = path1 ? bn1_g : bn2_g;
    const float* beta = path1 ? bn1_b : bn2_b;
    float* dst = path1 ? ss : (ss + 1024);
    float sc = gamma[c] * rsqrtf(var + 1e-5f);
    dst[c] = sc;
    dst[512 + c] = beta[c] - mu * sc;
  }
}

// ---------------------------------------------------------------------------
// 3-NN search only: warp-synchronous, register-resident distances.
// 8 dst points/block, one warp/point. Outputs weights + global feats1 rows.
// ---------------------------------------------------------------------------
__global__ void __launch_bounds__(256) knn(
    const float* __restrict__ xyz2, const float* __restrict__ xyz1,
    float4* __restrict__ kw, int4* __restrict__ ki) {
  __shared__ float sx[1024], sy[1024], sz[1024];  // xyz1 SoA (12 KB)

  const int tid = threadIdx.x;
  const int w = tid >> 5, lane = tid & 31;
  const int b = blockIdx.x >> 9;
  const int nb = (blockIdx.x & 511) * 8;

  const float* src = xyz1 + (size_t)b * 3072;
  for (int i = tid; i < 1024; i += 256) {
    sx[i] = src[3 * i + 0];
    sy[i] = src[3 * i + 1];
    sz[i] = src[3 * i + 2];
  }
  __syncthreads();

  const int n = nb + w;
  const int p = b * 4096 + n;
  const float* pd = xyz2 + (size_t)p * 3;
  const float px = pd[0], py = pd[1], pz = pd[2];
  const float pp = px * px + py * py + pz * pz;

  float d[32];
#pragma unroll
  for (int j = 0; j < 32; j++) {
    int s = lane + j * 32;
    float xx = sx[s], yy = sy[s], zz = sz[s];
    d[j] = pp + (xx * xx + yy * yy + zz * zz) -
           2.0f * (px * xx + py * yy + pz * zz);
  }

  float bv[3];
  int bi3[3];
#pragma unroll
  for (int round = 0; round < 3; round++) {
    float m = d[0];
#pragma unroll
    for (int j = 1; j < 32; j++) m = fminf(m, d[j]);
#pragma unroll
    for (int off = 16; off; off >>= 1)
      m = fminf(m, __shfl_xor_sync(0xffffffffu, m, off));
    int li = 0x7fffffff;
#pragma unroll
    for (int j = 0; j < 32; j++)
      if (d[j] == m) li = min(li, lane + j * 32);
#pragma unroll
    for (int off = 16; off; off >>= 1)
      li = min(li, __shfl_xor_sync(0xffffffffu, li, off));
    bv[round] = m;
    bi3[round] = li;
    if ((li & 31) == lane) {
      const int slot = li >> 5;
#pragma unroll
      for (int j = 0; j < 32; j++)
        if (j == slot) d[j] = 1e30f;
    }
  }

  if (lane == 0) {
    float w0 = 1.0f / (bv[0] + 1e-8f);
    float w1 = 1.0f / (bv[1] + 1e-8f);
    float w2 = 1.0f / (bv[2] + 1e-8f);
    float inv = 1.0f / (w0 + w1 + w2);
    kw[p] = float4{w0 * inv, w1 * inv, w2 * inv, 0.0f};
    ki[p] = int4{b * 1024 + bi3[0], b * 1024 + bi3[1], b * 1024 + bi3[2], 0};
  }
}

// ---------------------------------------------------------------------------
// Apply: gather 3 feats1 rows + feats2 row, fused BN+ReLU, weighted add.
// One warp per output row; low-register streaming kernel (high occupancy).
// ---------------------------------------------------------------------------
__global__ void __launch_bounds__(256) apply_add(
    const float* __restrict__ feats1, const float* __restrict__ feats2,
    const float4* __restrict__ kw, const int4* __restrict__ ki,
    const float* __restrict__ ss1, const float* __restrict__ ss2,
    float* __restrict__ outF) {
  const int lane = threadIdx.x & 31;
  const int row = blockIdx.x * 8 + (threadIdx.x >> 5);

  const float4 wv = kw[row];
  const int4 id = ki[row];
  const float w0 = wv.x, w1 = wv.y, w2 = wv.z;

  const float4* f0 = reinterpret_cast<const float4*>(feats1 + (size_t)id.x * 512);
  const float4* f1 = reinterpret_cast<const float4*>(feats1 + (size_t)id.y * 512);
  const float4* f2 = reinterpret_cast<const float4*>(feats1 + (size_t)id.z * 512);
  const float4* g = reinterpret_cast<const float4*>(feats2 + (size_t)row * 512);
  float4* o = reinterpret_cast<float4*>(outF + (size_t)row * 512);
  const float4* SC1 = reinterpret_cast<const float4*>(ss1);
  const float4* SH1 = reinterpret_cast<const float4*>(ss1 + 512);
  const float4* SC2 = reinterpret_cast<const float4*>(ss2);
  const float4* SH2 = reinterpret_cast<const float4*>(ss2 + 512);

#pragma unroll
  for (int c4 = lane; c4 < 128; c4 += 32) {
    float4 a0 = f0[c4], a1 = f1[c4], a2 = f2[c4], gg = g[c4];
    float4 sc1 = SC1[c4], sh1 = SH1[c4], sc2 = SC2[c4], sh2 = SH2[c4];
    a0.x = fmaxf(fmaf(a0.x, sc1.x, sh1.x), 0.0f);
    a0.y = fmaxf(fmaf(a0.y, sc1.y, sh1.y), 0.0f);
    a0.z = fmaxf(fmaf(a0.z, sc1.z, sh1.z), 0.0f);
    a0.w = fmaxf(fmaf(a0.w, sc1.w, sh1.w), 0.0f);
    a1.x = fmaxf(fmaf(a1.x, sc1.x, sh1.x), 0.0f);
    a1.y = fmaxf(fmaf(a1.y, sc1.y, sh1.y), 0.0f);
    a1.z = fmaxf(fmaf(a1.z, sc1.z, sh1.z), 0.0f);
    a1.w = fmaxf(fmaf(a1.w, sc1.w, sh1.w), 0.0f);
    a2.x = fmaxf(fmaf(a2.x, sc1.x, sh1.x), 0.0f);
    a2.y = fmaxf(fmaf(a2.y, sc1.y, sh1.y), 0.0f);
    a2.z = fmaxf(fmaf(a2.z, sc1.z, sh1.z), 0.0f);
    a2.w = fmaxf(fmaf(a2.w, sc1.w, sh1.w), 0.0f);
    gg.x = fmaxf(fmaf(gg.x, sc2.x, sh2.x), 0.0f);
    gg.y = fmaxf(fmaf(gg.y, sc2.y, sh2.y), 0.0f);
    gg.z = fmaxf(fmaf(gg.z, sc2.z, sh2.z), 0.0f);
    gg.w = fmaxf(fmaf(gg.w, sc2.w, sh2.w), 0.0f);
    float4 r;
    r.x = w0 * a0.x + w1 * a1.x + w2 * a2.x + gg.x;
    r.y = w0 * a0.y + w1 * a1.y + w2 * a2.y + gg.y;
    r.z = w0 * a0.z + w1 * a1.z + w2 * a2.z + gg.z;
    r.w = w0 * a0.w + w1 * a1.w + w2 * a2.w + gg.w;
    o[c4] = r;
  }
}

// ---------------------------------------------------------------------------
extern "C" void kernel_launch(void* const* d_in, const int* in_sizes, int n_in,
                              void* d_out, int out_size) {
  const float* xyz1 = (const float*)d_in[0];
  const float* points1 = (const float*)d_in[1];
  const float* xyz2 = (const float*)d_in[2];
  const float* points2 = (const float*)d_in[3];
  const float* fc1_w = (const float*)d_in[4];
  const float* fc1_b = (const float*)d_in[5];
  const float* bn1_g = (const float*)d_in[6];
  const float* bn1_b = (const float*)d_in[7];
  const float* fc2_w = (const float*)d_in[8];
  const float* fc2_b = (const float*)d_in[9];
  const float* bn2_g = (const float*)d_in[10];
  const float* bn2_b = (const float*)d_in[11];
  float* out = (float*)d_out;

  float *h1, *h2, *part, *ss;
  float4* kw;
  int4* ki;
  __nv_bfloat16 *w1h, *w1l, *w2h, *w2l;
  cudaGetSymbolAddress((void**)&h1, g_h1);
  cudaGetSymbolAddress((void**)&h2, g_h2);
  cudaGetSymbolAddress((void**)&part, g_part);
  cudaGetSymbolAddress((void**)&ss, g_ss);
  cudaGetSymbolAddress((void**)&kw, g_kw);
  cudaGetSymbolAddress((void**)&ki, g_ki);
  cudaGetSymbolAddress((void**)&w1h, g_w1h);
  cudaGetSymbolAddress((void**)&w1l, g_w1l);
  cudaGetSymbolAddress((void**)&w2h, g_w2h);
  cudaGetSymbolAddress((void**)&w2l, g_w2l);

  cudaFuncSetAttribute(gemm_all, cudaFuncAttributeMaxDynamicSharedMemorySize,
                       GEMM_SMEM);

  const size_t featElems = (size_t)16 * 4096 * 512;
  const size_t totalOut = (size_t)out_size;
  const size_t xyzElems = totalOut > featElems ? totalOut - featElems : 0;

  // launch 1: weight transpose + split
  wsplit_all<<<dim3(48, 16), 256>>>(fc1_w, w1h, w1l, fc2_w, w2h, w2l);

  // launch 2: 3-NN search (independent of GEMMs)
  knn<<<8192, 256>>>(xyz2, xyz1, kw, ki);

  // launch 3: BOTH GEMMs (fc2 blocks 0..1023, fc1 blocks 1024..1279)
  gemm_all<<<1280, 512, GEMM_SMEM>>>(points1, w1h, w1l, fc1_b, h1, points2,
                                     w2h, w2l, fc2_b, h2, part);

  // launch 4: BN stats for both paths
  stats_finalize_all<<<1024, 256>>>(part, bn1_g, bn1_b, bn2_g, bn2_b, ss);

  // Output: [xyz2 passthrough | apply(bnrelu(h1) gather) + bnrelu(h2)]
  if (xyzElems > 0) {
    cudaMemcpyAsync(out, xyz2, xyzElems * sizeof(float),
                    cudaMemcpyDeviceToDevice);
  }
  // launch 5: streaming gather+BN+add (high occupancy)
  apply_add<<<8192, 256>>>(h1, h2, kw, ki, ss, ss + 1024, out + xyzElems);
}